// round 9
// baseline (speedup 1.0000x reference)
#include <cuda_runtime.h>
#include <cuda_bf16.h>
#include <math.h>
#include <stdint.h>

// ===========================================================================
// YOLOv8 head via bf16 mma.sync implicit GEMM (shifted-GEMM conv).
//   conv3x3(pad1) == sum over 9 kernel offsets k of GEMM:
//      D[co, p] += W_k[co, ci] * Xpad[p + off_k, ci]
// R9: block 128co x 288px, 12 warps (2M x 6N) of 64x48 -> 3 warps/SMSP
//     (latency hiding) AND 27.4 FLOP/smem-byte (under crossbar cap).
// ===========================================================================

#define ATOT 33600

// per-level xpad/ypad region offsets (halves)
#define OFF_P3 262144
#define OFF_P4 27398144
#define OFF_P5 41431040
#define XPAD_TOTAL 48918528

__device__ __align__(256) __nv_bfloat16 g_xpad[XPAD_TOTAL];
__device__ __align__(256) __nv_bfloat16 g_ypad[XPAD_TOTAL];
__device__ __align__(256) float         g_y2  [8 * 25600 * 128];
__device__ __align__(256) __nv_bfloat16 g_wr1 [9 * 512 * 512];
__device__ __align__(256) __nv_bfloat16 g_wr2 [9 * 512 * 512];

__device__ __forceinline__ uint32_t smem_u32(const void* p) {
    return (uint32_t)__cvta_generic_to_shared(p);
}
__device__ __forceinline__ void cp_async16(uint32_t dst, const void* src) {
    asm volatile("cp.async.cg.shared.global [%0], [%1], 16;"
                 :: "r"(dst), "l"(__cvta_generic_to_global(src)) : "memory");
}
__device__ __forceinline__ void cp_commit() {
    asm volatile("cp.async.commit_group;" ::: "memory");
}
__device__ __forceinline__ void ldsm_x4(uint32_t& r0, uint32_t& r1,
                                        uint32_t& r2, uint32_t& r3, uint32_t a) {
    asm volatile("ldmatrix.sync.aligned.m8n8.x4.shared.b16 {%0,%1,%2,%3}, [%4];"
                 : "=r"(r0), "=r"(r1), "=r"(r2), "=r"(r3) : "r"(a));
}
__device__ __forceinline__ void mma_bf16(float& d0, float& d1, float& d2, float& d3,
                                         uint32_t a0, uint32_t a1, uint32_t a2, uint32_t a3,
                                         uint32_t b0, uint32_t b1) {
    asm volatile(
        "mma.sync.aligned.m16n8k16.row.col.f32.bf16.bf16.f32 "
        "{%0,%1,%2,%3}, {%4,%5,%6,%7}, {%8,%9}, {%0,%1,%2,%3};"
        : "+f"(d0), "+f"(d1), "+f"(d2), "+f"(d3)
        : "r"(a0), "r"(a1), "r"(a2), "r"(a3), "r"(b0), "r"(b1));
}

// ---------------------------------------------------------------------------
// weight repack: W(co,ci,3,3) fp32 -> Wrep[k][co][ci] bf16
// ---------------------------------------------------------------------------
__global__ void wrepack_kernel(const float* __restrict__ w,
                               __nv_bfloat16* __restrict__ wr, int C)
{
    int idx = blockIdx.x * blockDim.x + threadIdx.x;   // co*C + ci
    if (idx >= C * C) return;
#pragma unroll
    for (int k = 0; k < 9; k++)
        wr[(size_t)k * C * C + idx] = __float2bfloat16_rn(w[(size_t)idx * 9 + k]);
}

// ---------------------------------------------------------------------------
// pad+transpose: NCHW fp32 -> Xpad[n][p][ci] bf16 (interior pixels only)
// ---------------------------------------------------------------------------
__global__ void pad_transpose_kernel(const float* __restrict__ in,
                                     __nv_bfloat16* __restrict__ Xp,
                                     int C, int H, int W, int Wp, int Np)
{
    __shared__ float t[32][33];
    const int HW = H * W;
    const int q0 = blockIdx.x * 32;
    const int c0 = blockIdx.y * 32;
    const int n  = blockIdx.z;
    const int tx = threadIdx.x, ty = threadIdx.y;

    const float* inN = in + (size_t)n * C * HW;
#pragma unroll
    for (int j = 0; j < 4; j++) {
        int c = c0 + ty + j * 8;
        t[ty + j * 8][tx] = inN[(size_t)c * HW + q0 + tx];
    }
    __syncthreads();
    __nv_bfloat16* XpN = Xp + (size_t)n * Np * C;
#pragma unroll
    for (int j = 0; j < 4; j++) {
        int q = q0 + ty + j * 8;
        int py = q / W, px = q - py * W;
        int p = (py + 1) * Wp + px + 1;
        XpN[(size_t)p * C + c0 + tx] = __float2bfloat16_rn(t[tx][ty + j * 8]);
    }
}

// ---------------------------------------------------------------------------
// conv GEMM: D[128 co x 288 px] = sum_{k,ci} Wrep_k * Xpad(+off_k)
// 12 warps (2M x 6N), warp tile 64x48, mma m16n8k16 bf16, K-chunk 64,
// 3-stage cp.async pipeline, ldmatrix fragments.
// mode 0: bf16 padded [p][co]; mode 1: fp32 [q][co].
// ---------------------------------------------------------------------------
#define NPX     288                     // pixels per block
#define KS      72                      // halves per smem row (64 + 8 pad)
#define A_H     (128 * KS)              // halves, A tile
#define B_H     (NPX * KS)              // halves, B tile
#define STAGEH  (A_H + B_H)             // halves per stage
#define OSTRIDE 132

__global__ void __launch_bounds__(384, 1)
conv_gemm_kernel(const __nv_bfloat16* __restrict__ X,
                 const __nv_bfloat16* __restrict__ wrep,
                 const float* __restrict__ scale,
                 const float* __restrict__ bias,
                 void* __restrict__ Yv,
                 int C, int W, int Wp, int Np, int mode)
{
    extern __shared__ __nv_bfloat16 dsm[];   // 3 stages of [A(128xKS) | B(NPXxKS)]

    const int tid    = threadIdx.x;
    const int lane   = tid & 31;
    const int wid    = tid >> 5;
    const int warp_m = (wid >= 6) ? 1 : 0;  // 0..1
    const int warp_n = wid - warp_m * 6;    // 0..5
    const int p0     = blockIdx.x * NPX;
    const int co0    = blockIdx.y * 128;
    const int n      = blockIdx.z;

    const __nv_bfloat16* Ximg = X + (size_t)n * Np * C;
    const int NC = 9 * (C >> 6);        // K-chunks of 64 ci

    float acc[4][6][4];
#pragma unroll
    for (int mi = 0; mi < 4; mi++)
#pragma unroll
        for (int ni = 0; ni < 6; ni++)
#pragma unroll
            for (int r = 0; r < 4; r++) acc[mi][ni][r] = 0.f;

    const uint32_t smem0 = smem_u32(dsm);

    auto load_chunk = [&](int c, int buf) {
        const int k   = c % 9;
        const int cic = c / 9;
        const int off = (k / 3 - 1) * Wp + (k % 3 - 1);
        const __nv_bfloat16* Asrc = wrep + ((size_t)k * C + co0) * C + cic * 64;
        const __nv_bfloat16* Bsrc = Ximg + (long long)(p0 + off) * C + cic * 64;
        const uint32_t sAb = smem0 + buf * (STAGEH * 2);
        const uint32_t sBb = sAb + A_H * 2;
        // A: 128 rows x 8 float4 = 1024 elems; 384 threads -> 3 iters w/ guard
#pragma unroll
        for (int i = 0; i < 3; i++) {
            int e = tid + i * 384;
            if (e < 1024) {
                int r = e >> 3, f = e & 7;
                cp_async16(sAb + (r * KS + f * 8) * 2, Asrc + (size_t)r * C + f * 8);
            }
        }
        // B: 288 rows x 8 float4 = 2304 elems; 384 threads -> 6 iters exact
#pragma unroll
        for (int i = 0; i < 6; i++) {
            int e = tid + i * 384, r = e >> 3, f = e & 7;
            cp_async16(sBb + (r * KS + f * 8) * 2, Bsrc + (long long)r * C + f * 8);
        }
        cp_commit();
    };

    // per-thread ldmatrix byte offsets (stage-relative)
    uint32_t aOff[4], bOff[3];
#pragma unroll
    for (int mi = 0; mi < 4; mi++) {
        int row = warp_m * 64 + mi * 16 + (lane & 15);
        aOff[mi] = (uint32_t)((row * KS + ((lane >> 4) << 3)) * 2);
    }
#pragma unroll
    for (int np = 0; np < 3; np++) {
        int px = warp_n * 48 + np * 16 + ((lane >> 4) << 3) + (lane & 7);
        bOff[np] = (uint32_t)((px * KS + (((lane >> 3) & 1) << 3)) * 2) + A_H * 2;
    }

    load_chunk(0, 0);
    if (NC > 1) load_chunk(1, 1);

    int buf = 0;
    for (int c = 0; c < NC; c++) {
        if (c + 1 < NC)
            asm volatile("cp.async.wait_group 1;" ::: "memory");
        else
            asm volatile("cp.async.wait_group 0;" ::: "memory");
        __syncthreads();

        if (c + 2 < NC) {
            int nb = buf + 2; if (nb >= 3) nb -= 3;
            load_chunk(c + 2, nb);
        }

        const uint32_t sbase = smem0 + buf * (STAGEH * 2);
#pragma unroll
        for (int ks = 0; ks < 4; ks++) {
            const uint32_t ko = ks * 32;    // 16 halves
            uint32_t af[4][4], bf[3][4];
#pragma unroll
            for (int mi = 0; mi < 4; mi++)
                ldsm_x4(af[mi][0], af[mi][1], af[mi][2], af[mi][3],
                        sbase + aOff[mi] + ko);
#pragma unroll
            for (int np = 0; np < 3; np++)
                ldsm_x4(bf[np][0], bf[np][1], bf[np][2], bf[np][3],
                        sbase + bOff[np] + ko);
#pragma unroll
            for (int mi = 0; mi < 4; mi++)
#pragma unroll
                for (int ni = 0; ni < 6; ni++)
                    mma_bf16(acc[mi][ni][0], acc[mi][ni][1], acc[mi][ni][2], acc[mi][ni][3],
                             af[mi][0], af[mi][1], af[mi][2], af[mi][3],
                             bf[ni >> 1][(ni & 1) * 2], bf[ni >> 1][(ni & 1) * 2 + 1]);
        }
        buf++; if (buf == 3) buf = 0;
    }
    __syncthreads();

    // ---- epilogue: BN+ReLU, stage [px][co] fp32 tile in smem ----
    float* st = (float*)dsm;    // 288 x OSTRIDE x 4B = 152KB <= 180KB
    {
        const int g  = lane >> 2;
        const int q2 = (lane & 3) << 1;
#pragma unroll
        for (int mi = 0; mi < 4; mi++) {
            const int col0 = warp_m * 64 + mi * 16 + g;
            const float s0 = __ldg(scale + co0 + col0),     b0 = __ldg(bias + co0 + col0);
            const float s1 = __ldg(scale + co0 + col0 + 8), b1 = __ldg(bias + co0 + col0 + 8);
#pragma unroll
            for (int ni = 0; ni < 6; ni++) {
                const int pxl = warp_n * 48 + ni * 8 + q2;
                st[pxl * OSTRIDE + col0]           = fmaxf(fmaf(acc[mi][ni][0], s0, b0), 0.f);
                st[(pxl + 1) * OSTRIDE + col0]     = fmaxf(fmaf(acc[mi][ni][1], s0, b0), 0.f);
                st[pxl * OSTRIDE + col0 + 8]       = fmaxf(fmaf(acc[mi][ni][2], s1, b1), 0.f);
                st[(pxl + 1) * OSTRIDE + col0 + 8] = fmaxf(fmaf(acc[mi][ni][3], s1, b1), 0.f);
            }
        }
    }
    __syncthreads();

#pragma unroll 1
    for (int i = 0; i < 24; i++) {
        int idx = tid + i * 384;
        int r = idx >> 5, f = idx & 31;     // 288 rows x 32 float4-groups
        int p = p0 + r;
        if (p < Np) {
            int py = p / Wp, px = p - py * Wp;
            if (py >= 1 && py <= W && px >= 1 && px <= W) {
                float4 v = *(const float4*)&st[r * OSTRIDE + f * 4];
                if (mode == 0) {
                    __nv_bfloat16* Yb = (__nv_bfloat16*)Yv + (size_t)n * Np * C;
                    __nv_bfloat162 h0 = __floats2bfloat162_rn(v.x, v.y);
                    __nv_bfloat162 h1 = __floats2bfloat162_rn(v.z, v.w);
                    uint2 pk;
                    pk.x = *reinterpret_cast<uint32_t*>(&h0);
                    pk.y = *reinterpret_cast<uint32_t*>(&h1);
                    *(uint2*)&Yb[(size_t)p * C + co0 + f * 4] = pk;
                } else {
                    float* Yf = (float*)Yv + (size_t)n * (size_t)(W * W) * C;
                    *(float4*)&Yf[((size_t)(py - 1) * W + (px - 1)) * C + co0 + f * 4] = v;
                }
            }
        }
    }
}

// ---------------------------------------------------------------------------
// 1x1 conv (C->5) + decode + sigmoid. warp-per-pixel, y2 layout [n][q][C].
// ---------------------------------------------------------------------------
__global__ void __launch_bounds__(256)
conv1x1_decode_kernel(const float* __restrict__ y2,
                      const float* __restrict__ wf,
                      const float* __restrict__ bf,
                      float* __restrict__ out,
                      int C, int W, int HW, int aoff, float stride)
{
    __shared__ float s_wf[5 * 512];
    for (int t = threadIdx.x; t < 5 * C; t += 256) s_wf[t] = wf[t];
    __syncthreads();

    const int wid  = threadIdx.x >> 5;
    const int lane = threadIdx.x & 31;
    const int q = blockIdx.x * 8 + wid;
    const int n = blockIdx.y;
    if (q >= HW) return;

    const float* yq = y2 + ((size_t)n * HW + q) * C;
    float a[5] = {0.f, 0.f, 0.f, 0.f, 0.f};
    const int iters = C >> 7;
    for (int it = 0; it < iters; it++) {
        int cb = it * 128 + lane * 4;
        float4 v = *(const float4*)(yq + cb);
#pragma unroll
        for (int j = 0; j < 5; j++) {
            const float* wj = s_wf + j * C + cb;
            a[j] += v.x * wj[0] + v.y * wj[1] + v.z * wj[2] + v.w * wj[3];
        }
    }
#pragma unroll
    for (int j = 0; j < 5; j++)
#pragma unroll
        for (int o = 16; o; o >>= 1)
            a[j] += __shfl_xor_sync(0xffffffffu, a[j], o);

    if (lane == 0) {
        float a0 = a[0] + bf[0], a1 = a[1] + bf[1], a2 = a[2] + bf[2];
        float a3 = a[3] + bf[3], a4 = a[4] + bf[4];
        int py = q / W, px = q - py * W;
        float ax = px + 0.5f, ay = py + 0.5f;
        float cx = (ax + 0.5f * (a2 - a0)) * stride;
        float cy = (ay + 0.5f * (a3 - a1)) * stride;
        float bw = (a2 + a0) * stride;
        float bh = (a3 + a1) * stride;
        float cls = 1.f / (1.f + expf(-a4));
        size_t base = (size_t)n * 5 * ATOT + (size_t)aoff + q;
        out[base]                    = cx;
        out[base + (size_t)ATOT]     = cy;
        out[base + 2 * (size_t)ATOT] = bw;
        out[base + 3 * (size_t)ATOT] = bh;
        out[base + 4 * (size_t)ATOT] = cls;
    }
}

// ---------------------------------------------------------------------------
// Host
// ---------------------------------------------------------------------------
#define CONV_SMEM (3 * STAGEH * 2)   // 179,712 B

static void run_level(void* const* d_in, int xin, int widx,
                      __nv_bfloat16* xpad, __nv_bfloat16* ypad, float* y2,
                      __nv_bfloat16* wr1, __nv_bfloat16* wr2, float* out,
                      int B, int C, int H, int aoff, float stride)
{
    const float* x  = (const float*)d_in[xin];
    const float* w1 = (const float*)d_in[widx + 0];
    const float* s1 = (const float*)d_in[widx + 1];
    const float* b1 = (const float*)d_in[widx + 2];
    const float* w2 = (const float*)d_in[widx + 3];
    const float* s2 = (const float*)d_in[widx + 4];
    const float* b2 = (const float*)d_in[widx + 5];
    const float* wf = (const float*)d_in[widx + 6];
    const float* bf = (const float*)d_in[widx + 7];

    const int W = H, Wp = W + 2, Np = Wp * Wp, HW = H * W;

    wrepack_kernel<<<(C * C + 255) / 256, 256>>>(w1, wr1, C);
    wrepack_kernel<<<(C * C + 255) / 256, 256>>>(w2, wr2, C);

    dim3 gp(HW / 32, C / 32, B);
    pad_transpose_kernel<<<gp, dim3(32, 8)>>>(x, xpad, C, H, W, Wp, Np);

    const int pixTiles = (Np + NPX - 1) / NPX;
    dim3 gc(pixTiles, C / 128, B);
    conv_gemm_kernel<<<gc, 384, CONV_SMEM>>>(xpad, wr1, s1, b1, ypad, C, W, Wp, Np, 0);
    conv_gemm_kernel<<<gc, 384, CONV_SMEM>>>(ypad, wr2, s2, b2, y2,   C, W, Wp, Np, 1);

    dim3 gd((HW + 7) / 8, B);
    conv1x1_decode_kernel<<<gd, 256>>>(y2, wf, bf, out, C, W, HW, aoff, stride);
}

extern "C" void kernel_launch(void* const* d_in, const int* in_sizes, int n_in,
                              void* d_out, int out_size)
{
    __nv_bfloat16 *xpad, *ypad, *wr1, *wr2;
    float *y2;
    cudaGetSymbolAddress((void**)&xpad, g_xpad);
    cudaGetSymbolAddress((void**)&ypad, g_ypad);
    cudaGetSymbolAddress((void**)&y2,   g_y2);
    cudaGetSymbolAddress((void**)&wr1,  g_wr1);
    cudaGetSymbolAddress((void**)&wr2,  g_wr2);

    cudaFuncSetAttribute(conv_gemm_kernel,
                         cudaFuncAttributeMaxDynamicSharedMemorySize, CONV_SMEM);

    const int B = in_sizes[0] / (128 * 160 * 160);
    float* out = (float*)d_out;

    run_level(d_in, 0,  3, xpad + OFF_P3, ypad + OFF_P3, y2, wr1, wr2, out, B, 128, 160, 0,     8.f);
    run_level(d_in, 1, 11, xpad + OFF_P4, ypad + OFF_P4, y2, wr1, wr2, out, B, 256,  80, 25600, 16.f);
    run_level(d_in, 2, 19, xpad + OFF_P5, ypad + OFF_P5, y2, wr1, wr2, out, B, 512,  40, 32000, 32.f);
}

// round 10
// speedup vs baseline: 1.2519x; 1.2519x over previous
#include <cuda_runtime.h>
#include <cuda_bf16.h>
#include <math.h>
#include <stdint.h>

// ===========================================================================
// YOLOv8 head via bf16 mma.sync implicit GEMM (shifted-GEMM conv).
//   conv3x3(pad1) == sum over 9 kernel offsets k of GEMM:
//      D[co, p] += W_k[co, ci] * Xpad[p + off_k, ci]
// R10: R6 kernel config (64x32 warp tile, 8 warps, 2 CTAs/SM — best measured)
//      + ALL THREE LEVELS BATCHED per conv launch (flat grid, level descriptors,
//      longest CTAs first) to kill wave-quantization tails.
// ===========================================================================

#define ATOT 33600

// per-level xpad/ypad region offsets (halves)
#define OFF_P3 262144
#define OFF_P4 27398144
#define OFF_P5 41431040
#define XPAD_TOTAL 48918528

// per-level y2 offsets (floats)
#define Y2_P3 0
#define Y2_P4 26214400
#define Y2_P5 39321600
#define Y2_TOTAL 45875200

// per-level wrep offsets (halves): p5 first
#define WR_P5 0
#define WR_P4 2359296
#define WR_P3 2949120
#define WR_TOTAL 3096576

__device__ __align__(256) __nv_bfloat16 g_xpad[XPAD_TOTAL];
__device__ __align__(256) __nv_bfloat16 g_ypad[XPAD_TOTAL];
__device__ __align__(256) float         g_y2  [Y2_TOTAL];
__device__ __align__(256) __nv_bfloat16 g_wr1 [WR_TOTAL];
__device__ __align__(256) __nv_bfloat16 g_wr2 [WR_TOTAL];

struct LevelParams {
    const __nv_bfloat16* X;
    const __nv_bfloat16* Wr;
    const float* scale;
    const float* bias;
    void* Y;
    int C, W, Wp, Np;
    int start;      // first flat CTA index of this level
    int tiles;      // pixel tiles = ceil(Np/128)
    int cgrp;       // C / 128
};

__device__ __forceinline__ uint32_t smem_u32(const void* p) {
    return (uint32_t)__cvta_generic_to_shared(p);
}
__device__ __forceinline__ void cp_async16(uint32_t dst, const void* src) {
    asm volatile("cp.async.cg.shared.global [%0], [%1], 16;"
                 :: "r"(dst), "l"(__cvta_generic_to_global(src)) : "memory");
}
__device__ __forceinline__ void cp_commit() {
    asm volatile("cp.async.commit_group;" ::: "memory");
}
__device__ __forceinline__ void ldsm_x4(uint32_t& r0, uint32_t& r1,
                                        uint32_t& r2, uint32_t& r3, uint32_t a) {
    asm volatile("ldmatrix.sync.aligned.m8n8.x4.shared.b16 {%0,%1,%2,%3}, [%4];"
                 : "=r"(r0), "=r"(r1), "=r"(r2), "=r"(r3) : "r"(a));
}
__device__ __forceinline__ void mma_bf16(float& d0, float& d1, float& d2, float& d3,
                                         uint32_t a0, uint32_t a1, uint32_t a2, uint32_t a3,
                                         uint32_t b0, uint32_t b1) {
    asm volatile(
        "mma.sync.aligned.m16n8k16.row.col.f32.bf16.bf16.f32 "
        "{%0,%1,%2,%3}, {%4,%5,%6,%7}, {%8,%9}, {%0,%1,%2,%3};"
        : "+f"(d0), "+f"(d1), "+f"(d2), "+f"(d3)
        : "r"(a0), "r"(a1), "r"(a2), "r"(a3), "r"(b0), "r"(b1));
}

// ---------------------------------------------------------------------------
// weight repack: W(co,ci,3,3) fp32 -> Wrep[k][co][ci] bf16
// ---------------------------------------------------------------------------
__global__ void wrepack_kernel(const float* __restrict__ w,
                               __nv_bfloat16* __restrict__ wr, int C)
{
    int idx = blockIdx.x * blockDim.x + threadIdx.x;   // co*C + ci
    if (idx >= C * C) return;
#pragma unroll
    for (int k = 0; k < 9; k++)
        wr[(size_t)k * C * C + idx] = __float2bfloat16_rn(w[(size_t)idx * 9 + k]);
}

// ---------------------------------------------------------------------------
// pad+transpose: NCHW fp32 -> Xpad[n][p][ci] bf16 (interior pixels only)
// ---------------------------------------------------------------------------
__global__ void pad_transpose_kernel(const float* __restrict__ in,
                                     __nv_bfloat16* __restrict__ Xp,
                                     int C, int H, int W, int Wp, int Np)
{
    __shared__ float t[32][33];
    const int HW = H * W;
    const int q0 = blockIdx.x * 32;
    const int c0 = blockIdx.y * 32;
    const int n  = blockIdx.z;
    const int tx = threadIdx.x, ty = threadIdx.y;

    const float* inN = in + (size_t)n * C * HW;
#pragma unroll
    for (int j = 0; j < 4; j++) {
        int c = c0 + ty + j * 8;
        t[ty + j * 8][tx] = inN[(size_t)c * HW + q0 + tx];
    }
    __syncthreads();
    __nv_bfloat16* XpN = Xp + (size_t)n * Np * C;
#pragma unroll
    for (int j = 0; j < 4; j++) {
        int q = q0 + ty + j * 8;
        int py = q / W, px = q - py * W;
        int p = (py + 1) * Wp + px + 1;
        XpN[(size_t)p * C + c0 + tx] = __float2bfloat16_rn(t[tx][ty + j * 8]);
    }
}

// ---------------------------------------------------------------------------
// batched conv GEMM over 3 levels: D[128 co x 128 px] = sum Wrep_k * Xpad(+off)
// 8 warps (2M x 4N), warp tile 64x32, mma m16n8k16 bf16, K-chunk 64,
// 3-stage cp.async pipeline, ldmatrix fragments. Level from flat blockIdx.x.
// mode 0: bf16 padded [p][co]; mode 1: fp32 [q][co].
// ---------------------------------------------------------------------------
#define KS      72                      // halves per smem row (64 + 8 pad)
#define STAGEH  (2 * 128 * KS)          // halves per stage (A tile + B tile)
#define OSTRIDE 132

__global__ void __launch_bounds__(256, 2)
conv_gemm_kernel(LevelParams l0, LevelParams l1, LevelParams l2, int mode)
{
    extern __shared__ __nv_bfloat16 dsm[];   // 3 stages of [A(128xKS) | B(128xKS)]

    const int x = blockIdx.x;
    const LevelParams L = (x >= l2.start) ? l2 : ((x >= l1.start) ? l1 : l0);

    const int idx  = x - L.start;
    const int tile = idx % L.tiles;
    const int rest = idx / L.tiles;
    const int cog  = rest % L.cgrp;
    const int n    = rest / L.cgrp;

    const int C = L.C, W = L.W, Wp = L.Wp, Np = L.Np;
    const int p0  = tile * 128;
    const int co0 = cog * 128;

    const int tid    = threadIdx.x;
    const int lane   = tid & 31;
    const int wid    = tid >> 5;
    const int warp_m = wid >> 2;        // 0..1
    const int warp_n = wid & 3;         // 0..3

    const __nv_bfloat16* Ximg = L.X + (size_t)n * Np * C;
    const __nv_bfloat16* wrep = L.Wr;
    const int NC = 9 * (C >> 6);        // K-chunks of 64 ci

    float acc[4][4][4];
#pragma unroll
    for (int mi = 0; mi < 4; mi++)
#pragma unroll
        for (int ni = 0; ni < 4; ni++)
#pragma unroll
            for (int r = 0; r < 4; r++) acc[mi][ni][r] = 0.f;

    const uint32_t smem0 = smem_u32(dsm);

    auto load_chunk = [&](int c, int buf) {
        const int k   = c % 9;
        const int cic = c / 9;
        const int off = (k / 3 - 1) * Wp + (k % 3 - 1);
        const __nv_bfloat16* Asrc = wrep + ((size_t)k * C + co0) * C + cic * 64;
        const __nv_bfloat16* Bsrc = Ximg + (long long)(p0 + off) * C + cic * 64;
        const uint32_t sAb = smem0 + buf * (STAGEH * 2);
        const uint32_t sBb = sAb + 128 * KS * 2;
#pragma unroll
        for (int i = 0; i < 4; i++) {
            int e = tid + i * 256, r = e >> 3, f = e & 7;
            cp_async16(sAb + (r * KS + f * 8) * 2, Asrc + (size_t)r * C + f * 8);
            cp_async16(sBb + (r * KS + f * 8) * 2, Bsrc + (long long)r * C + f * 8);
        }
        cp_commit();
    };

    // per-thread ldmatrix byte offsets (stage-relative)
    uint32_t aOff[4], bOff[2];
#pragma unroll
    for (int mi = 0; mi < 4; mi++) {
        int row = warp_m * 64 + mi * 16 + (lane & 15);
        aOff[mi] = (uint32_t)((row * KS + ((lane >> 4) << 3)) * 2);
    }
#pragma unroll
    for (int np = 0; np < 2; np++) {
        int px = warp_n * 32 + np * 16 + ((lane >> 4) << 3) + (lane & 7);
        bOff[np] = (uint32_t)((px * KS + (((lane >> 3) & 1) << 3)) * 2) + 128 * KS * 2;
    }

    load_chunk(0, 0);
    if (NC > 1) load_chunk(1, 1);

    int buf = 0;
    for (int c = 0; c < NC; c++) {
        if (c + 1 < NC)
            asm volatile("cp.async.wait_group 1;" ::: "memory");
        else
            asm volatile("cp.async.wait_group 0;" ::: "memory");
        __syncthreads();

        if (c + 2 < NC) {
            int nb = buf + 2; if (nb >= 3) nb -= 3;
            load_chunk(c + 2, nb);
        }

        const uint32_t sbase = smem0 + buf * (STAGEH * 2);
#pragma unroll
        for (int ks = 0; ks < 4; ks++) {
            const uint32_t ko = ks * 32;    // 16 halves
            uint32_t af[4][4], bf[2][4];
#pragma unroll
            for (int mi = 0; mi < 4; mi++)
                ldsm_x4(af[mi][0], af[mi][1], af[mi][2], af[mi][3],
                        sbase + aOff[mi] + ko);
#pragma unroll
            for (int np = 0; np < 2; np++)
                ldsm_x4(bf[np][0], bf[np][1], bf[np][2], bf[np][3],
                        sbase + bOff[np] + ko);
#pragma unroll
            for (int mi = 0; mi < 4; mi++)
#pragma unroll
                for (int ni = 0; ni < 4; ni++)
                    mma_bf16(acc[mi][ni][0], acc[mi][ni][1], acc[mi][ni][2], acc[mi][ni][3],
                             af[mi][0], af[mi][1], af[mi][2], af[mi][3],
                             bf[ni >> 1][(ni & 1) * 2], bf[ni >> 1][(ni & 1) * 2 + 1]);
        }
        buf++; if (buf == 3) buf = 0;
    }
    __syncthreads();

    // ---- epilogue: BN+ReLU, stage [px][co] fp32 tile in smem ----
    float* st = (float*)dsm;
    {
        const int g  = lane >> 2;
        const int q2 = (lane & 3) << 1;
#pragma unroll
        for (int mi = 0; mi < 4; mi++) {
            const int col0 = warp_m * 64 + mi * 16 + g;
            const float s0 = __ldg(L.scale + co0 + col0),     b0 = __ldg(L.bias + co0 + col0);
            const float s1 = __ldg(L.scale + co0 + col0 + 8), b1 = __ldg(L.bias + co0 + col0 + 8);
#pragma unroll
            for (int ni = 0; ni < 4; ni++) {
                const int pxl = warp_n * 32 + ni * 8 + q2;
                st[pxl * OSTRIDE + col0]           = fmaxf(fmaf(acc[mi][ni][0], s0, b0), 0.f);
                st[(pxl + 1) * OSTRIDE + col0]     = fmaxf(fmaf(acc[mi][ni][1], s0, b0), 0.f);
                st[pxl * OSTRIDE + col0 + 8]       = fmaxf(fmaf(acc[mi][ni][2], s1, b1), 0.f);
                st[(pxl + 1) * OSTRIDE + col0 + 8] = fmaxf(fmaf(acc[mi][ni][3], s1, b1), 0.f);
            }
        }
    }
    __syncthreads();

#pragma unroll 1
    for (int i = 0; i < 16; i++) {
        int idx2 = tid + i * 256;
        int r = idx2 >> 5, f = idx2 & 31;
        int p = p0 + r;
        if (p < Np) {
            int py = p / Wp, px = p - py * Wp;
            if (py >= 1 && py <= W && px >= 1 && px <= W) {
                float4 v = *(const float4*)&st[r * OSTRIDE + f * 4];
                if (mode == 0) {
                    __nv_bfloat16* Yb = (__nv_bfloat16*)L.Y + (size_t)n * Np * C;
                    __nv_bfloat162 h0 = __floats2bfloat162_rn(v.x, v.y);
                    __nv_bfloat162 h1 = __floats2bfloat162_rn(v.z, v.w);
                    uint2 pk;
                    pk.x = *reinterpret_cast<uint32_t*>(&h0);
                    pk.y = *reinterpret_cast<uint32_t*>(&h1);
                    *(uint2*)&Yb[(size_t)p * C + co0 + f * 4] = pk;
                } else {
                    float* Yf = (float*)L.Y + (size_t)n * (size_t)(W * W) * C;
                    *(float4*)&Yf[((size_t)(py - 1) * W + (px - 1)) * C + co0 + f * 4] = v;
                }
            }
        }
    }
}

// ---------------------------------------------------------------------------
// 1x1 conv (C->5) + decode + sigmoid. warp-per-pixel, y2 layout [n][q][C].
// ---------------------------------------------------------------------------
__global__ void __launch_bounds__(256)
conv1x1_decode_kernel(const float* __restrict__ y2,
                      const float* __restrict__ wf,
                      const float* __restrict__ bf,
                      float* __restrict__ out,
                      int C, int W, int HW, int aoff, float stride)
{
    __shared__ float s_wf[5 * 512];
    for (int t = threadIdx.x; t < 5 * C; t += 256) s_wf[t] = wf[t];
    __syncthreads();

    const int wid  = threadIdx.x >> 5;
    const int lane = threadIdx.x & 31;
    const int q = blockIdx.x * 8 + wid;
    const int n = blockIdx.y;
    if (q >= HW) return;

    const float* yq = y2 + ((size_t)n * HW + q) * C;
    float a[5] = {0.f, 0.f, 0.f, 0.f, 0.f};
    const int iters = C >> 7;
    for (int it = 0; it < iters; it++) {
        int cb = it * 128 + lane * 4;
        float4 v = *(const float4*)(yq + cb);
#pragma unroll
        for (int j = 0; j < 5; j++) {
            const float* wj = s_wf + j * C + cb;
            a[j] += v.x * wj[0] + v.y * wj[1] + v.z * wj[2] + v.w * wj[3];
        }
    }
#pragma unroll
    for (int j = 0; j < 5; j++)
#pragma unroll
        for (int o = 16; o; o >>= 1)
            a[j] += __shfl_xor_sync(0xffffffffu, a[j], o);

    if (lane == 0) {
        float a0 = a[0] + bf[0], a1 = a[1] + bf[1], a2 = a[2] + bf[2];
        float a3 = a[3] + bf[3], a4 = a[4] + bf[4];
        int py = q / W, px = q - py * W;
        float ax = px + 0.5f, ay = py + 0.5f;
        float cx = (ax + 0.5f * (a2 - a0)) * stride;
        float cy = (ay + 0.5f * (a3 - a1)) * stride;
        float bw = (a2 + a0) * stride;
        float bh = (a3 + a1) * stride;
        float cls = 1.f / (1.f + expf(-a4));
        size_t base = (size_t)n * 5 * ATOT + (size_t)aoff + q;
        out[base]                    = cx;
        out[base + (size_t)ATOT]     = cy;
        out[base + 2 * (size_t)ATOT] = bw;
        out[base + 3 * (size_t)ATOT] = bh;
        out[base + 4 * (size_t)ATOT] = cls;
    }
}

// ---------------------------------------------------------------------------
// Host
// ---------------------------------------------------------------------------
#define CONV_SMEM (3 * STAGEH * 2)   // 110,592 B

extern "C" void kernel_launch(void* const* d_in, const int* in_sizes, int n_in,
                              void* d_out, int out_size)
{
    __nv_bfloat16 *xpad, *ypad, *wr1, *wr2;
    float *y2;
    cudaGetSymbolAddress((void**)&xpad, g_xpad);
    cudaGetSymbolAddress((void**)&ypad, g_ypad);
    cudaGetSymbolAddress((void**)&y2,   g_y2);
    cudaGetSymbolAddress((void**)&wr1,  g_wr1);
    cudaGetSymbolAddress((void**)&wr2,  g_wr2);

    cudaFuncSetAttribute(conv_gemm_kernel,
                         cudaFuncAttributeMaxDynamicSharedMemorySize, CONV_SMEM);

    const int B = in_sizes[0] / (128 * 160 * 160);
    float* out = (float*)d_out;

    // level static tables: order p5, p4, p3 (longest CTAs first)
    const int   Cs[3]   = {512, 256, 128};
    const int   Ws[3]   = {40, 80, 160};
    const int   xin[3]  = {2, 1, 0};
    const int   widx[3] = {19, 11, 3};
    const int   xoff[3] = {OFF_P5, OFF_P4, OFF_P3};
    const int   y2off[3]= {Y2_P5, Y2_P4, Y2_P3};
    const int   wroff[3]= {WR_P5, WR_P4, WR_P3};
    const int   aoff[3] = {32000, 25600, 0};
    const float strd[3] = {32.f, 16.f, 8.f};

    LevelParams L1[3], L2[3];
    int start = 0;
    for (int i = 0; i < 3; i++) {
        const int C = Cs[i], W = Ws[i], Wp = W + 2, Np = Wp * Wp;
        const int tiles = (Np + 127) / 128, cgrp = C / 128;

        // weight repack (both convs)
        wrepack_kernel<<<(C * C + 255) / 256, 256>>>(
            (const float*)d_in[widx[i] + 0], wr1 + wroff[i], C);
        wrepack_kernel<<<(C * C + 255) / 256, 256>>>(
            (const float*)d_in[widx[i] + 3], wr2 + wroff[i], C);

        // pad+transpose input
        dim3 gp((W * W) / 32, C / 32, B);
        pad_transpose_kernel<<<gp, dim3(32, 8)>>>(
            (const float*)d_in[xin[i]], xpad + xoff[i], C, W, W, Wp, Np);

        L1[i] = { xpad + xoff[i], wr1 + wroff[i],
                  (const float*)d_in[widx[i] + 1], (const float*)d_in[widx[i] + 2],
                  (void*)(ypad + xoff[i]), C, W, Wp, Np, start, tiles, cgrp };
        L2[i] = { ypad + xoff[i], wr2 + wroff[i],
                  (const float*)d_in[widx[i] + 4], (const float*)d_in[widx[i] + 5],
                  (void*)(y2 + y2off[i]), C, W, Wp, Np, start, tiles, cgrp };
        start += tiles * cgrp * B;
    }

    // batched convs: one launch per conv index, all levels
    conv_gemm_kernel<<<start, 256, CONV_SMEM>>>(L1[0], L1[1], L1[2], 0);
    conv_gemm_kernel<<<start, 256, CONV_SMEM>>>(L2[0], L2[1], L2[2], 1);

    // decode per level
    for (int i = 0; i < 3; i++) {
        const int W = Ws[i], HW = W * W, C = Cs[i];
        dim3 gd((HW + 7) / 8, B);
        conv1x1_decode_kernel<<<gd, 256>>>(
            y2 + y2off[i], (const float*)d_in[widx[i] + 6],
            (const float*)d_in[widx[i] + 7], out, C, W, HW, aoff[i], strd[i]);
    }
}